// round 4
// baseline (speedup 1.0000x reference)
#include <cuda_runtime.h>
#include <cuda_bf16.h>
#include <cstdint>

// x: [4,16,4096,16] f32 -> out: [4,16,4096,273] f32
//   out[..., 0]      = 1
//   out[..., 1:17]   = x * 0.5
//   out[..., 17:273] = outer(x,x).flatten * 0.17677669529663687
//
// R3 was L1/smem-port bound (76.6%): 8 scalar LDS + table LDS per float4 of
// output tripled the L1 work vs the stores alone. Rework: thread=row,
// all operands in registers, outputs staged to smem with conflict-free
// STS.32 (stride 273 mod 32 = 17, coprime), then ONE 1D TMA bulk store
// (cp.async.bulk.global.shared::cta) drains the whole 34944B block —
// no STG wavefronts, no operand LDS on the L1 port.

#define D 16
#define FEAT 273
#define ROWS 32                         // rows per block = lanes per block
#define BLOCK_FLOATS (ROWS * FEAT)      // 8736
#define BLOCK_BYTES  (BLOCK_FLOATS * 4) // 34944, multiple of 16

__global__ __launch_bounds__(32) void taylor_exp_kernel(
    const float* __restrict__ x, float* __restrict__ out)
{
    __shared__ __align__(128) float s[BLOCK_FLOATS];   // 34944 B static

    const int lane = threadIdx.x;
    const long long row0 = (long long)blockIdx.x * ROWS;

    const float LIN = 0.5f;                     // 1/RRD
    const float SQS = 0.42044820762685725f;     // sqrt(1/(sqrt(2)*4))

    // ---- load this thread's row (16 floats) into registers ----
    const float4* xin = reinterpret_cast<const float4*>(x + (row0 + lane) * D);
    float4 v0 = __ldg(&xin[0]);
    float4 v1 = __ldg(&xin[1]);
    float4 v2 = __ldg(&xin[2]);
    float4 v3 = __ldg(&xin[3]);

    float xr[16];
    xr[0]=v0.x; xr[1]=v0.y; xr[2]=v0.z; xr[3]=v0.w;
    xr[4]=v1.x; xr[5]=v1.y; xr[6]=v1.z; xr[7]=v1.w;
    xr[8]=v2.x; xr[9]=v2.y; xr[10]=v2.z; xr[11]=v2.w;
    xr[12]=v3.x; xr[13]=v3.y; xr[14]=v3.z; xr[15]=v3.w;

    float y[16];
    #pragma unroll
    for (int k = 0; k < 16; ++k) y[k] = xr[k] * SQS;

    // ---- emit 273 outputs for this row into smem (conflict-free STS.32) ----
    float* r = s + lane * FEAT;
    r[0] = 1.0f;
    #pragma unroll
    for (int k = 0; k < 16; ++k) r[1 + k] = xr[k] * LIN;
    #pragma unroll
    for (int i = 0; i < 16; ++i) {
        #pragma unroll
        for (int j = 0; j < 16; ++j) {
            r[17 + i * 16 + j] = y[i] * y[j];
        }
    }

    __syncthreads();

    // ---- single 1D TMA bulk store: smem -> global ----
    if (lane == 0) {
        float* gdst = out + (long long)blockIdx.x * BLOCK_FLOATS;
        unsigned saddr;
        asm volatile("{ .reg .u64 t; cvta.to.shared.u64 t, %1; cvt.u32.u64 %0, t; }"
                     : "=r"(saddr) : "l"(s));
        asm volatile("fence.proxy.async.shared::cta;" ::: "memory");
        asm volatile("cp.async.bulk.global.shared::cta.bulk_group [%0], [%1], %2;"
                     :: "l"(gdst), "r"(saddr), "r"((unsigned)BLOCK_BYTES)
                     : "memory");
        asm volatile("cp.async.bulk.commit_group;" ::: "memory");
        asm volatile("cp.async.bulk.wait_group 0;" ::: "memory");
    }
}

extern "C" void kernel_launch(void* const* d_in, const int* in_sizes, int n_in,
                              void* d_out, int out_size)
{
    const float* x = (const float*)d_in[0];
    float* out = (float*)d_out;

    int n_rows = in_sizes[0] / D;        // 262144
    int n_blocks = n_rows / ROWS;        // 8192

    taylor_exp_kernel<<<n_blocks, 32>>>(x, out);
}